// round 4
// baseline (speedup 1.0000x reference)
#include <cuda_runtime.h>
#include <math.h>

#define NB 64
#define HH 224
#define WW 224
#define C1 24
#define C2 48
#define H2 112
#define H4 56
#define EPSV 1e-5f
#define K2LEN 150528   /* C2*H4*H4 */
#define KCH 512
#define NCHUNK 294     /* 294*512 = 150528 */

typedef unsigned long long u64;

// ---------------- packed f32x2 helpers (sm_100+ PTX) ------------------------
__device__ __forceinline__ u64 pk2(float a, float b) {
    u64 r;
    asm("mov.b64 %0, {%1, %2};" : "=l"(r) : "r"(__float_as_uint(a)), "r"(__float_as_uint(b)));
    return r;
}
__device__ __forceinline__ void unpk2(u64 v, float& a, float& b) {
    unsigned lo, hi;
    asm("mov.b64 {%0, %1}, %2;" : "=r"(lo), "=r"(hi) : "l"(v));
    a = __uint_as_float(lo); b = __uint_as_float(hi);
}
__device__ __forceinline__ u64 fma2(u64 a, u64 b, u64 c) {
    u64 d;
    asm("fma.rn.f32x2 %0, %1, %2, %3;" : "=l"(d) : "l"(a), "l"(b), "l"(c));
    return d;
}
__device__ __forceinline__ u64 dupw(float w) {
    unsigned u = __float_as_uint(w);
    return (u64)u | ((u64)u << 32);
}

// ---------------- scratch (static __device__, no allocation) ----------------
__device__ float g_x1[NB*C1*H2*H2];          // pooled conv1 output
__device__ float g_x2[NB*C2*H4*H4];          // RAW pooled-max conv2 output (pre-BN)
__device__ double g_s1[C1*64];               // 512B stride -> distinct LTS slices
__device__ double g_q1[C1*64];
__device__ double g_s2[C2*64];
__device__ double g_q2[C2*64];
__device__ float g_bn1s[C1], g_bn1b[C1];
__device__ float g_bn2s[C2], g_bn2b[C2];
__device__ float g_part[NCHUNK*NB*C2];
__device__ float g_feat[NB*C2];
__device__ float g_theta[NB*6];

__global__ void k_zero() {
    int i = blockIdx.x*256 + threadIdx.x;
    if (i < C1*64) { g_s1[i] = 0.0; g_q1[i] = 0.0; }
    if (i < C2*64) { g_s2[i] = 0.0; g_q2[i] = 0.0; }
}

// ---------------- conv1 statistics pass (f32x2) -----------------------------
__global__ void __launch_bounds__(256) k_conv1_stats(const float* __restrict__ x,
        const float* __restrict__ w, const float* __restrict__ bias) {
    __shared__ u64 ws2[C1*9];
    __shared__ float wb[C1];
    for (int i = threadIdx.x; i < C1*9; i += 256) ws2[i] = dupw(w[i]);
    if (threadIdx.x < C1) wb[threadIdx.x] = bias[threadIdx.x];
    __syncthreads();

    float sum[C1], sq[C1];
#pragma unroll
    for (int c = 0; c < C1; c++) { sum[c] = 0.f; sq[c] = 0.f; }

    const int nthreads = 784*256;
    int t0 = blockIdx.x*256 + threadIdx.x;
#pragma unroll 1
    for (int it = 0; it < 4; it++) {
        int q = t0 + it*nthreads;
        int b   = q / (HH*56);
        int rem = q - b*(HH*56);
        int row = rem / 56;
        int qc  = rem - row*56;
        const float* xb = x + b*HH*WW;
        float tap[3][6];
#pragma unroll
        for (int r = 0; r < 3; r++) {
            int gy = row - 1 + r;
            bool vy = (unsigned)gy < HH;
#pragma unroll
            for (int cc = 0; cc < 6; cc++) {
                int gx = qc*4 - 1 + cc;
                tap[r][cc] = (vy && (unsigned)gx < WW) ? xb[gy*WW + gx] : 0.f;
            }
        }
        u64 tp[3][5];
#pragma unroll
        for (int r = 0; r < 3; r++)
#pragma unroll
        for (int cc = 0; cc < 5; cc++) tp[r][cc] = pk2(tap[r][cc], tap[r][cc+1]);

#pragma unroll
        for (int c = 0; c < C1; c++) {
            u64 a01 = 0ull, a23 = 0ull;
#pragma unroll
            for (int r = 0; r < 3; r++)
#pragma unroll
            for (int k = 0; k < 3; k++) {
                u64 wv = ws2[c*9 + r*3 + k];
                a01 = fma2(wv, tp[r][k],   a01);
                a23 = fma2(wv, tp[r][k+2], a23);
            }
            float v0, v1, v2, v3, bc = wb[c];
            unpk2(a01, v0, v1); unpk2(a23, v2, v3);
            v0 += bc; v1 += bc; v2 += bc; v3 += bc;
            sum[c] += (v0+v1) + (v2+v3);
            sq[c]   = fmaf(v0,v0, fmaf(v1,v1, fmaf(v2,v2, fmaf(v3,v3, sq[c]))));
        }
    }
#pragma unroll
    for (int c = 0; c < C1; c++) {
        float s = sum[c], t = sq[c];
        for (int o = 16; o > 0; o >>= 1) {
            s += __shfl_down_sync(0xffffffffu, s, o);
            t += __shfl_down_sync(0xffffffffu, t, o);
        }
        if ((threadIdx.x & 31) == 0) {
            atomicAdd(&g_s1[c*64], (double)s);
            atomicAdd(&g_q1[c*64], (double)t);
        }
    }
}

__global__ void k_fin1(const float* __restrict__ g, const float* __restrict__ b) {
    int c = threadIdx.x;
    if (c >= C1) return;
    double N = (double)NB*HH*WW;
    double m = g_s1[c*64] / N;
    double v = g_q1[c*64] / N - m*m;
    float sc = g[c] * rsqrtf((float)v + EPSV);
    g_bn1s[c] = sc;
    g_bn1b[c] = b[c] - (float)m * sc;
}

// ---------------- conv1 apply + BN + ReLU + maxpool2 (f32x2) ----------------
__global__ void __launch_bounds__(256) k_conv1_apply(const float* __restrict__ x,
        const float* __restrict__ w, const float* __restrict__ bias) {
    __shared__ u64 ws2[C1*9];
    __shared__ float wb[C1], bs[C1], bb[C1];
    for (int i = threadIdx.x; i < C1*9; i += 256) ws2[i] = dupw(w[i]);
    if (threadIdx.x < C1) {
        wb[threadIdx.x] = bias[threadIdx.x];
        bs[threadIdx.x] = g_bn1s[threadIdx.x];
        bb[threadIdx.x] = g_bn1b[threadIdx.x];
    }
    __syncthreads();

    int idx = blockIdx.x*256 + threadIdx.x;   // 64*112*112 exact
    int b   = idx / (H2*H2);
    int rem = idx - b*(H2*H2);
    int py  = rem / H2;
    int px  = rem - py*H2;
    const float* xb = x + b*HH*WW;

    float tap[4][4];
#pragma unroll
    for (int r = 0; r < 4; r++) {
        int gy = 2*py - 1 + r;
        bool vy = (unsigned)gy < HH;
#pragma unroll
        for (int cc = 0; cc < 4; cc++) {
            int gx = 2*px - 1 + cc;
            tap[r][cc] = (vy && (unsigned)gx < WW) ? xb[gy*WW + gx] : 0.f;
        }
    }
    u64 tp[4][3];
#pragma unroll
    for (int r = 0; r < 4; r++)
#pragma unroll
    for (int k = 0; k < 3; k++) tp[r][k] = pk2(tap[r][k], tap[r][k+1]);

    float* o1 = g_x1 + b*C1*H2*H2 + py*H2 + px;
#pragma unroll
    for (int c = 0; c < C1; c++) {
        u64 aT = 0ull, aB = 0ull;          // (v00,v01), (v10,v11)
#pragma unroll
        for (int r = 0; r < 3; r++)
#pragma unroll
        for (int k = 0; k < 3; k++) {
            u64 wv = ws2[c*9 + r*3 + k];
            aT = fma2(wv, tp[r][k],   aT);
            aB = fma2(wv, tp[r+1][k], aB);
        }
        float v00, v01, v10, v11, bc = wb[c];
        unpk2(aT, v00, v01); unpk2(aB, v10, v11);
        float sc = bs[c], sh = bb[c];
        v00 = fmaf(v00+bc, sc, sh); v01 = fmaf(v01+bc, sc, sh);
        v10 = fmaf(v10+bc, sc, sh); v11 = fmaf(v11+bc, sc, sh);
        float m = fmaxf(fmaxf(v00, v01), fmaxf(v10, v11));
        o1[c*H2*H2] = fmaxf(m, 0.f);
    }
}

// ---------------- conv2 (24->48) f32x2 + fused BN stats + fused maxpool -----
// block: 16x8 pixel tile, all 48 co. thread: 6 co x 4 px (column of 4 rows).
// Writes RAW pooled max directly to g_x2 (BN gamma>0 -> BN/ReLU commute w/ max).
__global__ void __launch_bounds__(256) k_conv2(const float* __restrict__ wt,
                                               const float* __restrict__ bias) {
    __shared__ float Is[C1*200];   // 24 ci x 10 rows x stride 20 = 19.2 KB
    __shared__ u64 Ws2[54*C2];     // 6 ci x 9 taps x 48 co duplicated = 20.7 KB

    int blk = blockIdx.x;                // 64 * 98
    int b   = blk / 98;
    int rem = blk - b*98;
    int tqy = rem / 7;
    int ty  = tqy * 8;
    int tx  = (rem - tqy*7) * 16;

    const float* x1b = g_x1 + b*C1*H2*H2;
    for (int i = threadIdx.x; i < C1*180; i += 256) {
        int ci = i / 180;
        int r2 = i - ci*180;
        int r  = r2 / 18;
        int c  = r2 - r*18;
        int gy = ty - 1 + r;
        int gx = tx - 1 + c;
        float v = ((unsigned)gy < H2 && (unsigned)gx < H2) ? x1b[(ci*H2 + gy)*H2 + gx] : 0.f;
        Is[ci*200 + r*20 + c] = v;
    }

    int lane  = threadIdx.x & 31;
    int warp  = threadIdx.x >> 5;        // co-group
    int colx  = lane & 15;
    int rbase = (lane >> 4) << 2;        // 0 or 4

    u64 acc[6][2];                       // [co][(rows 0,1)|(rows 2,3)]
#pragma unroll
    for (int j = 0; j < 6; j++) { acc[j][0] = 0ull; acc[j][1] = 0ull; }

#pragma unroll 1
    for (int g = 0; g < 4; g++) {        // 4 chunks of 6 ci
        __syncthreads();
        for (int i = threadIdx.x; i < 54*C2; i += 256) {
            int co = i / 54;
            int kk = i - co*54;
            Ws2[kk*C2 + co] = dupw(wt[co*216 + g*54 + kk]);
        }
        __syncthreads();
#pragma unroll 1
        for (int cl = 0; cl < 6; cl++) {
            const float* Ip = Is + (g*6 + cl)*200;
#pragma unroll
            for (int ky = 0; ky < 3; ky++) {
#pragma unroll
                for (int kx = 0; kx < 3; kx++) {
                    const u64* Wp = Ws2 + (cl*9 + ky*3 + kx)*C2 + warp*6;
                    float i0 = Ip[(rbase + ky + 0)*20 + colx + kx];
                    float i1 = Ip[(rbase + ky + 1)*20 + colx + kx];
                    float i2 = Ip[(rbase + ky + 2)*20 + colx + kx];
                    float i3 = Ip[(rbase + ky + 3)*20 + colx + kx];
                    u64 p01 = pk2(i0, i1);
                    u64 p23 = pk2(i2, i3);
#pragma unroll
                    for (int j = 0; j < 6; j++) {
                        u64 wv = Wp[j];                   // LDS.64 broadcast
                        acc[j][0] = fma2(wv, p01, acc[j][0]);
                        acc[j][1] = fma2(wv, p23, acc[j][1]);
                    }
                }
            }
        }
    }

    // epilogue: bias, stats, 2x2 pool (rows in-thread, cols via shfl_xor)
    int pooy = (ty + rbase) >> 1;
    int poox = (tx + colx) >> 1;
    bool wr  = (colx & 1) == 0;
#pragma unroll
    for (int j = 0; j < 6; j++) {
        int co = warp*6 + j;
        float bco = __ldg(&bias[co]);
        float v0, v1, v2, v3;
        unpk2(acc[j][0], v0, v1);
        unpk2(acc[j][1], v2, v3);
        v0 += bco; v1 += bco; v2 += bco; v3 += bco;
        float s  = (v0+v1) + (v2+v3);
        float qq = fmaf(v0,v0, fmaf(v1,v1, fmaf(v2,v2, v3*v3)));
        // vertical pool
        float pr0 = fmaxf(v0, v1);
        float pr1 = fmaxf(v2, v3);
        // horizontal pool across neighbor column
        float o0 = __shfl_xor_sync(0xffffffffu, pr0, 1);
        float o1 = __shfl_xor_sync(0xffffffffu, pr1, 1);
        pr0 = fmaxf(pr0, o0);
        pr1 = fmaxf(pr1, o1);
        if (wr) {
            float* dst = g_x2 + ((b*C2 + co)*H4 + pooy)*H4 + poox;
            dst[0]  = pr0;
            dst[H4] = pr1;
        }
        for (int o = 16; o > 0; o >>= 1) {
            s  += __shfl_down_sync(0xffffffffu, s,  o);
            qq += __shfl_down_sync(0xffffffffu, qq, o);
        }
        if (lane == 0) {
            atomicAdd(&g_s2[co*64], (double)s);
            atomicAdd(&g_q2[co*64], (double)qq);
        }
    }
}

__global__ void k_fin2(const float* __restrict__ g, const float* __restrict__ b) {
    int c = threadIdx.x;
    if (c >= C2) return;
    double N = (double)NB*H2*H2;
    double m = g_s2[c*64] / N;
    double v = g_q2[c*64] / N - m*m;
    float sc = g[c] * rsqrtf((float)v + EPSV);
    g_bn2s[c] = sc;
    g_bn2b[c] = b[c] - (float)m * sc;
}

// ---------------- feat GEMM split-K, BN+ReLU fused into x2 load -------------
__global__ void __launch_bounds__(256) k_feat_part(const float* __restrict__ fw) {
    __shared__ float xs[NB*33];
    __shared__ float wsm[C2*33];
    int k0  = blockIdx.x * KCH;
    int tid = threadIdx.x;
    int bi  = tid & 15;
    int oi  = tid >> 4;
    int kl  = tid & 31;
    int rr  = tid >> 5;
    float acc[4][3];
#pragma unroll
    for (int i = 0; i < 4; i++)
#pragma unroll
    for (int j = 0; j < 3; j++) acc[i][j] = 0.f;

#pragma unroll 1
    for (int kk = 0; kk < KCH; kk += 32) {
        __syncthreads();
        int kidx = k0 + kk + kl;
        int ch   = kidx / (H4*H4);
        float sc = g_bn2s[ch], sh = g_bn2b[ch];
#pragma unroll
        for (int r = 0; r < 8; r++) {
            int bb = r*8 + rr;
            float raw = g_x2[bb*K2LEN + kidx];
            xs[bb*33 + kl] = fmaxf(fmaf(raw, sc, sh), 0.f);
        }
#pragma unroll
        for (int r = 0; r < 6; r++) {
            int oo = r*8 + rr;
            wsm[oo*33 + kl] = fw[(size_t)oo*K2LEN + kidx];
        }
        __syncthreads();
#pragma unroll
        for (int k = 0; k < 32; k++) {
            float xv[4], wv[3];
#pragma unroll
            for (int i = 0; i < 4; i++) xv[i] = xs[(bi*4 + i)*33 + k];
#pragma unroll
            for (int j = 0; j < 3; j++) wv[j] = wsm[(oi*3 + j)*33 + k];
#pragma unroll
            for (int i = 0; i < 4; i++)
#pragma unroll
            for (int j = 0; j < 3; j++)
                acc[i][j] = fmaf(xv[i], wv[j], acc[i][j]);
        }
    }
#pragma unroll
    for (int i = 0; i < 4; i++)
#pragma unroll
    for (int j = 0; j < 3; j++)
        g_part[(size_t)blockIdx.x*NB*C2 + (bi*4 + i)*C2 + (oi*3 + j)] = acc[i][j];
}

__global__ void k_feat_reduce(const float* __restrict__ fb) {
    int i = blockIdx.x*256 + threadIdx.x;
    if (i >= NB*C2) return;
    float s = 0.f;
    for (int n = 0; n < NCHUNK; n++) s += g_part[n*NB*C2 + i];
    g_feat[i] = s + fb[i % C2];
}

// ---------------- MLP head + theta build + tail outputs ---------------------
__global__ void k_head(const float* __restrict__ l1w, const float* __restrict__ l1b,
                       const float* __restrict__ l2w, const float* __restrict__ l2b,
                       float* __restrict__ out) {
    int b = threadIdx.x;
    if (b >= NB) return;
    float h[24];
#pragma unroll 1
    for (int j = 0; j < 24; j++) {
        float s = l1b[j];
        for (int k = 0; k < 48; k++)
            s = fmaf(l1w[j*48 + k], g_feat[b*48 + k], s);
        h[j] = fmaxf(s, 0.f);
    }
    float t[4];
#pragma unroll
    for (int i = 0; i < 4; i++) {
        float s = l2b[i];
#pragma unroll
        for (int j = 0; j < 24; j++)
            s = fmaf(l2w[i*24 + j], h[j], s);
        t[i] = s;
    }
    float tx = t[0], tyv = t[1], sc = t[2], an = t[3];
    float cs = cosf(an), sn = sinf(an);
    g_theta[b*6 + 0] =  sc*cs;
    g_theta[b*6 + 1] = -sc*sn;
    g_theta[b*6 + 2] =  tx;
    g_theta[b*6 + 3] =  sc*sn;
    g_theta[b*6 + 4] =  sc*cs;
    g_theta[b*6 + 5] =  tyv;
    out[NB*HH*WW +         b] = tx;
    out[NB*HH*WW +  64 +   b] = tyv;
    out[NB*HH*WW + 128 +   b] = sc;
    out[NB*HH*WW + 192 +   b] = an;
}

// ---------------- affine grid + bilinear sample -----------------------------
__device__ __forceinline__ float tapf(const float* __restrict__ xb,
                                      float xf, float yf, float wgt) {
    bool valid = (xf >= 0.f) & (xf < (float)WW) & (yf >= 0.f) & (yf < (float)HH);
    int xi = (int)fminf(fmaxf(xf, 0.f), (float)(WW-1));
    int yi = (int)fminf(fmaxf(yf, 0.f), (float)(HH-1));
    float v = __ldg(&xb[yi*WW + xi]);
    return valid ? v*wgt : 0.f;
}

__global__ void k_sample(const float* __restrict__ x, float* __restrict__ out) {
    int idx = blockIdx.x*256 + threadIdx.x;      // 64*224*224 exact
    int b   = idx / (HH*WW);
    int rem = idx - b*(HH*WW);
    int r   = rem / WW;
    int c   = rem - r*WW;
    float xsn = (2.f*c + 1.f)/(float)WW - 1.f;
    float ysn = (2.f*r + 1.f)/(float)HH - 1.f;
    const float* th = g_theta + b*6;
    float gx = th[0]*xsn + th[1]*ysn + th[2];
    float gy = th[3]*xsn + th[4]*ysn + th[5];
    float ix = ((gx + 1.f)*(float)WW - 1.f)*0.5f;
    float iy = ((gy + 1.f)*(float)HH - 1.f)*0.5f;
    float x0 = floorf(ix), y0 = floorf(iy);
    float x1 = x0 + 1.f,   y1 = y0 + 1.f;
    float wx1 = ix - x0, wx0 = 1.f - wx1;
    float wy1 = iy - y0, wy0 = 1.f - wy1;
    const float* xb = x + b*HH*WW;
    float o = tapf(xb, x0, y0, wx0*wy0)
            + tapf(xb, x1, y0, wx1*wy0)
            + tapf(xb, x0, y1, wx0*wy1)
            + tapf(xb, x1, y1, wx1*wy1);
    out[idx] = o;
}

// ---------------- launch ----------------------------------------------------
extern "C" void kernel_launch(void* const* d_in, const int* in_sizes, int n_in,
                              void* d_out, int out_size) {
    (void)in_sizes; (void)n_in; (void)out_size;
    const float* x    = (const float*)d_in[0];
    const float* c1w  = (const float*)d_in[1];
    const float* c1b  = (const float*)d_in[2];
    const float* bn1g = (const float*)d_in[3];
    const float* bn1b = (const float*)d_in[4];
    const float* c2w  = (const float*)d_in[5];
    const float* c2b  = (const float*)d_in[6];
    const float* bn2g = (const float*)d_in[7];
    const float* bn2b = (const float*)d_in[8];
    const float* fw   = (const float*)d_in[9];
    const float* fb   = (const float*)d_in[10];
    const float* l1w  = (const float*)d_in[11];
    const float* l1b  = (const float*)d_in[12];
    const float* l2w  = (const float*)d_in[13];
    const float* l2b  = (const float*)d_in[14];
    float* out = (float*)d_out;

    k_zero<<<12, 256>>>();
    k_conv1_stats<<<784, 256>>>(x, c1w, c1b);
    k_fin1<<<1, 32>>>(bn1g, bn1b);
    k_conv1_apply<<<3136, 256>>>(x, c1w, c1b);
    k_conv2<<<NB*98, 256>>>(c2w, c2b);
    k_fin2<<<1, 64>>>(bn2g, bn2b);
    k_feat_part<<<NCHUNK, 256>>>(fw);
    k_feat_reduce<<<12, 256>>>(fb);
    k_head<<<1, 64>>>(l1w, l1b, l2w, l2b, out);
    k_sample<<<(NB*HH*WW)/256, 256>>>(x, out);
}

// round 6
// speedup vs baseline: 1.5658x; 1.5658x over previous
#include <cuda_runtime.h>
#include <math.h>

#define NB 64
#define HH 224
#define WW 224
#define C1 24
#define C2 48
#define H2 112
#define H4 56
#define EPSV 1e-5f
#define K2LEN 150528   /* C2*H4*H4 */
#define KCH 512
#define NCHUNK 294     /* 294*512 = 150528 */

// ---------------- scratch (static __device__, no allocation) ----------------
__device__ float g_x1[NB*C1*H2*H2];          // RAW pooled conv1 output (pre-BN)
__device__ float g_x2[NB*C2*H4*H4];          // RAW pooled conv2 output (pre-BN)
__device__ double g_s1[C1*64];               // 512B stride -> distinct LTS slices
__device__ double g_q1[C1*64];
__device__ double g_s2[C2*64];
__device__ double g_q2[C2*64];
__device__ float g_bn1s[C1], g_bn1b[C1];
__device__ float g_bn2s[C2], g_bn2b[C2];
__device__ float g_part[NCHUNK*NB*C2];
__device__ float g_feat[NB*C2];
__device__ float g_theta[NB*6];

__global__ void k_zero() {
    int i = blockIdx.x*256 + threadIdx.x;
    if (i < C1*64) { g_s1[i] = 0.0; g_q1[i] = 0.0; }
    if (i < C2*64) { g_s2[i] = 0.0; g_q2[i] = 0.0; }
}

// ---------------- conv1 single pass: conv + stats + raw maxpool -------------
// one thread per pooled pixel; computes the 2x2 pre-pool quad for all 24 c,
// accumulates per-channel sum/sumsq, writes raw pooled max (BN applied later
// in conv2 staging: gamma=1>0 so BN/ReLU commute with max).
__global__ void __launch_bounds__(256) k_conv1(const float* __restrict__ x,
        const float* __restrict__ w, const float* __restrict__ bias) {
    __shared__ float ws[C1*9];
    __shared__ float wb[C1];
    __shared__ float bacc[C1*2];             // block stat accumulators (float)
    for (int i = threadIdx.x; i < C1*9; i += 256) ws[i] = w[i];
    if (threadIdx.x < C1) wb[threadIdx.x] = bias[threadIdx.x];
    if (threadIdx.x < C1*2) bacc[threadIdx.x] = 0.f;
    __syncthreads();

    int idx = blockIdx.x*256 + threadIdx.x;   // 64*112*112 exact
    int b   = idx / (H2*H2);
    int rem = idx - b*(H2*H2);
    int py  = rem / H2;
    int px  = rem - py*H2;
    const float* xb = x + b*HH*WW;

    float tap[4][4];
#pragma unroll
    for (int r = 0; r < 4; r++) {
        int gy = 2*py - 1 + r;
        bool vy = (unsigned)gy < HH;
#pragma unroll
        for (int cc = 0; cc < 4; cc++) {
            int gx = 2*px - 1 + cc;
            tap[r][cc] = (vy && (unsigned)gx < WW) ? xb[gy*WW + gx] : 0.f;
        }
    }
    int lane = threadIdx.x & 31;
    float* o1 = g_x1 + b*C1*H2*H2 + py*H2 + px;
#pragma unroll
    for (int c = 0; c < C1; c++) {
        float v00 = wb[c], v01 = wb[c], v10 = wb[c], v11 = wb[c];
#pragma unroll
        for (int r = 0; r < 3; r++)
#pragma unroll
        for (int k = 0; k < 3; k++) {
            float wv = ws[c*9 + r*3 + k];
            v00 = fmaf(wv, tap[r  ][k  ], v00);
            v01 = fmaf(wv, tap[r  ][k+1], v01);
            v10 = fmaf(wv, tap[r+1][k  ], v10);
            v11 = fmaf(wv, tap[r+1][k+1], v11);
        }
        // raw pooled max
        o1[c*H2*H2] = fmaxf(fmaxf(v00, v01), fmaxf(v10, v11));
        // stats over pre-pool values
        float s = (v00+v01) + (v10+v11);
        float q = fmaf(v00,v00, fmaf(v01,v01, fmaf(v10,v10, v11*v11)));
        for (int o = 16; o > 0; o >>= 1) {
            s += __shfl_down_sync(0xffffffffu, s, o);
            q += __shfl_down_sync(0xffffffffu, q, o);
        }
        if (lane == 0) {
            atomicAdd(&bacc[c],      s);
            atomicAdd(&bacc[C1 + c], q);
        }
    }
    __syncthreads();
    if (threadIdx.x < C1)
        atomicAdd(&g_s1[threadIdx.x*64], (double)bacc[threadIdx.x]);
    else if (threadIdx.x < C1*2)
        atomicAdd(&g_q1[(threadIdx.x-C1)*64], (double)bacc[threadIdx.x]);
}

__global__ void k_fin1(const float* __restrict__ g, const float* __restrict__ b) {
    int c = threadIdx.x;
    if (c >= C1) return;
    double N = (double)NB*HH*WW;
    double m = g_s1[c*64] / N;
    double v = g_q1[c*64] / N - m*m;
    float sc = g[c] * rsqrtf((float)v + EPSV);
    g_bn1s[c] = sc;
    g_bn1b[c] = b[c] - (float)m * sc;
}

// ---------------- conv2 (24->48) + BN1/ReLU on load + stats + fused pool ----
// block: 16x8 pixel tile, all 48 co. thread: 6 co x 4 px (column of 4 rows).
__global__ void __launch_bounds__(256) k_conv2(const float* __restrict__ wt,
                                               const float* __restrict__ bias) {
    __shared__ float Is[C1*200];   // 24 ci x 10 rows x stride 20 = 19.2 KB
    __shared__ float Ws[108*C2];   // 12 ci x 9 taps x 48 co = 20.7 KB
    __shared__ float b1s[C1], b1b[C1];

    if (threadIdx.x < C1) {
        b1s[threadIdx.x] = g_bn1s[threadIdx.x];
        b1b[threadIdx.x] = g_bn1b[threadIdx.x];
    }
    __syncthreads();

    int blk = blockIdx.x;                // 64 * 98
    int b   = blk / 98;
    int rem = blk - b*98;
    int tqy = rem / 7;
    int ty  = tqy * 8;
    int tx  = (rem - tqy*7) * 16;

    const float* x1b = g_x1 + b*C1*H2*H2;
    for (int i = threadIdx.x; i < C1*180; i += 256) {
        int ci = i / 180;
        int r2 = i - ci*180;
        int r  = r2 / 18;
        int c  = r2 - r*18;
        int gy = ty - 1 + r;
        int gx = tx - 1 + c;
        float v = ((unsigned)gy < H2 && (unsigned)gx < H2) ? x1b[(ci*H2 + gy)*H2 + gx] : 0.f;
        // apply BN1 + ReLU here (raw pooled -> activated)
        Is[ci*200 + r*20 + c] = fmaxf(fmaf(v, b1s[ci], b1b[ci]), 0.f);
    }

    int lane  = threadIdx.x & 31;
    int warp  = threadIdx.x >> 5;        // co-group
    int colx  = lane & 15;
    int rbase = (lane >> 4) << 2;        // 0 or 4 -> +80 floats = disjoint bank halves

    float acc[6][4];
#pragma unroll
    for (int j = 0; j < 6; j++)
#pragma unroll
    for (int i = 0; i < 4; i++) acc[j][i] = 0.f;

#pragma unroll 1
    for (int g = 0; g < 2; g++) {
        __syncthreads();
        for (int i = threadIdx.x; i < 108*C2; i += 256) {
            int co = i / 108;
            int kk = i - co*108;
            Ws[kk*C2 + co] = wt[co*216 + g*108 + kk];   // coalesced read
        }
        __syncthreads();
#pragma unroll 1
        for (int cl = 0; cl < 12; cl++) {
            const float* Ip = Is + (g*12 + cl)*200;
#pragma unroll
            for (int ky = 0; ky < 3; ky++) {
#pragma unroll
                for (int kx = 0; kx < 3; kx++) {
                    const float* Wp = Ws + (cl*9 + ky*3 + kx)*C2 + warp*6;
                    float wv[6], iv[4];
#pragma unroll
                    for (int j = 0; j < 6; j++) wv[j] = Wp[j];       // broadcast LDS
#pragma unroll
                    for (int i = 0; i < 4; i++)
                        iv[i] = Ip[(rbase + ky + i)*20 + colx + kx]; // conflict-free
#pragma unroll
                    for (int j = 0; j < 6; j++)
#pragma unroll
                    for (int i = 0; i < 4; i++)
                        acc[j][i] = fmaf(wv[j], iv[i], acc[j][i]);
                }
            }
        }
    }

    // epilogue: bias, stats, 2x2 pool (rows in-thread, cols via shfl_xor)
    int pooy = (ty + rbase) >> 1;
    int poox = (tx + colx) >> 1;
    bool wr  = (colx & 1) == 0;
#pragma unroll
    for (int j = 0; j < 6; j++) {
        int co = warp*6 + j;
        float bco = __ldg(&bias[co]);
        float v0 = acc[j][0] + bco;
        float v1 = acc[j][1] + bco;
        float v2 = acc[j][2] + bco;
        float v3 = acc[j][3] + bco;
        float s  = (v0+v1) + (v2+v3);
        float qq = fmaf(v0,v0, fmaf(v1,v1, fmaf(v2,v2, v3*v3)));
        float pr0 = fmaxf(v0, v1);                       // vertical pool
        float pr1 = fmaxf(v2, v3);
        float o0 = __shfl_xor_sync(0xffffffffu, pr0, 1); // horizontal pool
        float o1 = __shfl_xor_sync(0xffffffffu, pr1, 1);
        pr0 = fmaxf(pr0, o0);
        pr1 = fmaxf(pr1, o1);
        if (wr) {
            float* dst = g_x2 + ((b*C2 + co)*H4 + pooy)*H4 + poox;
            dst[0]  = pr0;
            dst[H4] = pr1;
        }
        for (int o = 16; o > 0; o >>= 1) {
            s  += __shfl_down_sync(0xffffffffu, s,  o);
            qq += __shfl_down_sync(0xffffffffu, qq, o);
        }
        if (lane == 0) {
            atomicAdd(&g_s2[co*64], (double)s);
            atomicAdd(&g_q2[co*64], (double)qq);
        }
    }
}

__global__ void k_fin2(const float* __restrict__ g, const float* __restrict__ b) {
    int c = threadIdx.x;
    if (c >= C2) return;
    double N = (double)NB*H2*H2;
    double m = g_s2[c*64] / N;
    double v = g_q2[c*64] / N - m*m;
    float sc = g[c] * rsqrtf((float)v + EPSV);
    g_bn2s[c] = sc;
    g_bn2b[c] = b[c] - (float)m * sc;
}

// ---------------- feat GEMM split-K, BN2+ReLU fused into x2 load ------------
__global__ void __launch_bounds__(256) k_feat_part(const float* __restrict__ fw) {
    __shared__ float xs[NB*33];
    __shared__ float wsm[C2*33];
    int k0  = blockIdx.x * KCH;
    int tid = threadIdx.x;
    int bi  = tid & 15;
    int oi  = tid >> 4;
    int kl  = tid & 31;
    int rr  = tid >> 5;
    float acc[4][3];
#pragma unroll
    for (int i = 0; i < 4; i++)
#pragma unroll
    for (int j = 0; j < 3; j++) acc[i][j] = 0.f;

#pragma unroll 1
    for (int kk = 0; kk < KCH; kk += 32) {
        __syncthreads();
        int kidx = k0 + kk + kl;
        int ch   = kidx / (H4*H4);
        float sc = g_bn2s[ch], sh = g_bn2b[ch];
#pragma unroll
        for (int r = 0; r < 8; r++) {
            int bb = r*8 + rr;
            float raw = g_x2[bb*K2LEN + kidx];
            xs[bb*33 + kl] = fmaxf(fmaf(raw, sc, sh), 0.f);
        }
#pragma unroll
        for (int r = 0; r < 6; r++) {
            int oo = r*8 + rr;
            wsm[oo*33 + kl] = fw[(size_t)oo*K2LEN + kidx];
        }
        __syncthreads();
#pragma unroll
        for (int k = 0; k < 32; k++) {
            float xv[4], wv[3];
#pragma unroll
            for (int i = 0; i < 4; i++) xv[i] = xs[(bi*4 + i)*33 + k];
#pragma unroll
            for (int j = 0; j < 3; j++) wv[j] = wsm[(oi*3 + j)*33 + k];
#pragma unroll
            for (int i = 0; i < 4; i++)
#pragma unroll
            for (int j = 0; j < 3; j++)
                acc[i][j] = fmaf(xv[i], wv[j], acc[i][j]);
        }
    }
#pragma unroll
    for (int i = 0; i < 4; i++)
#pragma unroll
    for (int j = 0; j < 3; j++)
        g_part[(size_t)blockIdx.x*NB*C2 + (bi*4 + i)*C2 + (oi*3 + j)] = acc[i][j];
}

__global__ void k_feat_reduce(const float* __restrict__ fb) {
    int i = blockIdx.x*256 + threadIdx.x;
    if (i >= NB*C2) return;
    float s = 0.f;
    for (int n = 0; n < NCHUNK; n++) s += g_part[n*NB*C2 + i];
    g_feat[i] = s + fb[i % C2];
}

// ---------------- MLP head + theta build + tail outputs ---------------------
__global__ void k_head(const float* __restrict__ l1w, const float* __restrict__ l1b,
                       const float* __restrict__ l2w, const float* __restrict__ l2b,
                       float* __restrict__ out) {
    int b = threadIdx.x;
    if (b >= NB) return;
    float h[24];
#pragma unroll 1
    for (int j = 0; j < 24; j++) {
        float s = l1b[j];
        for (int k = 0; k < 48; k++)
            s = fmaf(l1w[j*48 + k], g_feat[b*48 + k], s);
        h[j] = fmaxf(s, 0.f);
    }
    float t[4];
#pragma unroll
    for (int i = 0; i < 4; i++) {
        float s = l2b[i];
#pragma unroll
        for (int j = 0; j < 24; j++)
            s = fmaf(l2w[i*24 + j], h[j], s);
        t[i] = s;
    }
    float tx = t[0], tyv = t[1], sc = t[2], an = t[3];
    float cs = cosf(an), sn = sinf(an);
    g_theta[b*6 + 0] =  sc*cs;
    g_theta[b*6 + 1] = -sc*sn;
    g_theta[b*6 + 2] =  tx;
    g_theta[b*6 + 3] =  sc*sn;
    g_theta[b*6 + 4] =  sc*cs;
    g_theta[b*6 + 5] =  tyv;
    out[NB*HH*WW +         b] = tx;
    out[NB*HH*WW +  64 +   b] = tyv;
    out[NB*HH*WW + 128 +   b] = sc;
    out[NB*HH*WW + 192 +   b] = an;
}

// ---------------- affine grid + bilinear sample -----------------------------
__device__ __forceinline__ float tapf(const float* __restrict__ xb,
                                      float xf, float yf, float wgt) {
    bool valid = (xf >= 0.f) & (xf < (float)WW) & (yf >= 0.f) & (yf < (float)HH);
    int xi = (int)fminf(fmaxf(xf, 0.f), (float)(WW-1));
    int yi = (int)fminf(fmaxf(yf, 0.f), (float)(HH-1));
    float v = __ldg(&xb[yi*WW + xi]);
    return valid ? v*wgt : 0.f;
}

__global__ void k_sample(const float* __restrict__ x, float* __restrict__ out) {
    int idx = blockIdx.x*256 + threadIdx.x;      // 64*224*224 exact
    int b   = idx / (HH*WW);
    int rem = idx - b*(HH*WW);
    int r   = rem / WW;
    int c   = rem - r*WW;
    float xsn = (2.f*c + 1.f)/(float)WW - 1.f;
    float ysn = (2.f*r + 1.f)/(float)HH - 1.f;
    const float* th = g_theta + b*6;
    float gx = th[0]*xsn + th[1]*ysn + th[2];
    float gy = th[3]*xsn + th[4]*ysn + th[5];
    float ix = ((gx + 1.f)*(float)WW - 1.f)*0.5f;
    float iy = ((gy + 1.f)*(float)HH - 1.f)*0.5f;
    float x0 = floorf(ix), y0 = floorf(iy);
    float x1 = x0 + 1.f,   y1 = y0 + 1.f;
    float wx1 = ix - x0, wx0 = 1.f - wx1;
    float wy1 = iy - y0, wy0 = 1.f - wy1;
    const float* xb = x + b*HH*WW;
    float o = tapf(xb, x0, y0, wx0*wy0)
            + tapf(xb, x1, y0, wx1*wy0)
            + tapf(xb, x0, y1, wx0*wy1)
            + tapf(xb, x1, y1, wx1*wy1);
    out[idx] = o;
}

// ---------------- launch ----------------------------------------------------
extern "C" void kernel_launch(void* const* d_in, const int* in_sizes, int n_in,
                              void* d_out, int out_size) {
    (void)in_sizes; (void)n_in; (void)out_size;
    const float* x    = (const float*)d_in[0];
    const float* c1w  = (const float*)d_in[1];
    const float* c1b  = (const float*)d_in[2];
    const float* bn1g = (const float*)d_in[3];
    const float* bn1b = (const float*)d_in[4];
    const float* c2w  = (const float*)d_in[5];
    const float* c2b  = (const float*)d_in[6];
    const float* bn2g = (const float*)d_in[7];
    const float* bn2b = (const float*)d_in[8];
    const float* fw   = (const float*)d_in[9];
    const float* fb   = (const float*)d_in[10];
    const float* l1w  = (const float*)d_in[11];
    const float* l1b  = (const float*)d_in[12];
    const float* l2w  = (const float*)d_in[13];
    const float* l2b  = (const float*)d_in[14];
    float* out = (float*)d_out;

    k_zero<<<12, 256>>>();
    k_conv1<<<3136, 256>>>(x, c1w, c1b);
    k_fin1<<<1, 32>>>(bn1g, bn1b);
    k_conv2<<<NB*98, 256>>>(c2w, c2b);
    k_fin2<<<1, 64>>>(bn2g, bn2b);
    k_feat_part<<<NCHUNK, 256>>>(fw);
    k_feat_reduce<<<12, 256>>>(fb);
    k_head<<<1, 64>>>(l1w, l1b, l2w, l2b, out);
    k_sample<<<(NB*HH*WW)/256, 256>>>(x, out);
}

// round 9
// speedup vs baseline: 2.0966x; 1.3391x over previous
#include <cuda_runtime.h>
#include <math.h>

#define NB 64
#define HH 224
#define WW 224
#define C1 24
#define C2 48
#define H2 112
#define H4 56
#define EPSV 1e-5f
#define K2LEN 150528   /* C2*H4*H4 */
#define KCH 256
#define NCHUNK 588     /* 588*256 = 150528 */

// ---------------- scratch (static __device__, no allocation) ----------------
__device__ float g_x1[NB*C1*H2*H2];          // RAW pooled conv1 output (pre-BN)
__device__ float g_x2[NB*C2*H4*H4];          // RAW pooled conv2 output (pre-BN)
__device__ float g_U[16*C1*C2];              // Winograd-transformed conv2 weights
__device__ double g_s1[C1*64];               // 512B stride -> distinct LTS slices
__device__ double g_q1[C1*64];
__device__ double g_s2[C2*64];
__device__ double g_q2[C2*64];
__device__ float g_bn1s[C1], g_bn1b[C1];
__device__ float g_bn2s[C2], g_bn2b[C2];
__device__ float g_part[NCHUNK*NB*C2];
__device__ float g_feat[NB*C2];
__device__ float g_theta[NB*6];

__global__ void k_zero() {
    int i = blockIdx.x*256 + threadIdx.x;
    if (i < C1*64) { g_s1[i] = 0.0; g_q1[i] = 0.0; }
    if (i < C2*64) { g_s2[i] = 0.0; g_q2[i] = 0.0; }
}

// ---------------- Winograd weight transform U = G g G^T ---------------------
__global__ void k_prep(const float* __restrict__ wt) {
    int i = blockIdx.x*256 + threadIdx.x;
    if (i >= C2*C1) return;
    int co = i / C1, ci = i - co*C1;
    const float* g = wt + i*9;
    float T[4][3];
#pragma unroll
    for (int c = 0; c < 3; c++) {
        float g0 = g[0*3+c], g1 = g[1*3+c], g2 = g[2*3+c];
        T[0][c] = g0;
        T[1][c] = 0.5f*(g0 + g1 + g2);
        T[2][c] = 0.5f*(g0 - g1 + g2);
        T[3][c] = g2;
    }
#pragma unroll
    for (int pr = 0; pr < 4; pr++) {
        float t0 = T[pr][0], t1 = T[pr][1], t2 = T[pr][2];
        float U0 = t0;
        float U1 = 0.5f*(t0 + t1 + t2);
        float U2 = 0.5f*(t0 - t1 + t2);
        float U3 = t2;
        g_U[((pr*4+0)*C1 + ci)*C2 + co] = U0;
        g_U[((pr*4+1)*C1 + ci)*C2 + co] = U1;
        g_U[((pr*4+2)*C1 + ci)*C2 + co] = U2;
        g_U[((pr*4+3)*C1 + ci)*C2 + co] = U3;
    }
}

// ---------------- conv1 single pass: conv + stats + raw maxpool -------------
__global__ void __launch_bounds__(256) k_conv1(const float* __restrict__ x,
        const float* __restrict__ w, const float* __restrict__ bias) {
    __shared__ float ws[C1*9];
    __shared__ float wb[C1];
    __shared__ float bacc[C1*2];
    for (int i = threadIdx.x; i < C1*9; i += 256) ws[i] = w[i];
    if (threadIdx.x < C1) wb[threadIdx.x] = bias[threadIdx.x];
    if (threadIdx.x < C1*2) bacc[threadIdx.x] = 0.f;
    __syncthreads();

    int idx = blockIdx.x*256 + threadIdx.x;   // 64*112*112 exact
    int b   = idx / (H2*H2);
    int rem = idx - b*(H2*H2);
    int py  = rem / H2;
    int px  = rem - py*H2;
    const float* xb = x + b*HH*WW;

    float tap[4][4];
#pragma unroll
    for (int r = 0; r < 4; r++) {
        int gy = 2*py - 1 + r;
        bool vy = (unsigned)gy < HH;
#pragma unroll
        for (int cc = 0; cc < 4; cc++) {
            int gx = 2*px - 1 + cc;
            tap[r][cc] = (vy && (unsigned)gx < WW) ? xb[gy*WW + gx] : 0.f;
        }
    }
    int lane = threadIdx.x & 31;
    float* o1 = g_x1 + b*C1*H2*H2 + py*H2 + px;
#pragma unroll
    for (int c = 0; c < C1; c++) {
        float v00 = wb[c], v01 = wb[c], v10 = wb[c], v11 = wb[c];
#pragma unroll
        for (int r = 0; r < 3; r++)
#pragma unroll
        for (int k = 0; k < 3; k++) {
            float wv = ws[c*9 + r*3 + k];
            v00 = fmaf(wv, tap[r  ][k  ], v00);
            v01 = fmaf(wv, tap[r  ][k+1], v01);
            v10 = fmaf(wv, tap[r+1][k  ], v10);
            v11 = fmaf(wv, tap[r+1][k+1], v11);
        }
        o1[c*H2*H2] = fmaxf(fmaxf(v00, v01), fmaxf(v10, v11));
        float s = (v00+v01) + (v10+v11);
        float q = fmaf(v00,v00, fmaf(v01,v01, fmaf(v10,v10, v11*v11)));
        for (int o = 16; o > 0; o >>= 1) {
            s += __shfl_down_sync(0xffffffffu, s, o);
            q += __shfl_down_sync(0xffffffffu, q, o);
        }
        if (lane == 0) {
            atomicAdd(&bacc[c],      s);
            atomicAdd(&bacc[C1 + c], q);
        }
    }
    __syncthreads();
    if (threadIdx.x < C1)
        atomicAdd(&g_s1[threadIdx.x*64], (double)bacc[threadIdx.x]);
    else if (threadIdx.x < C1*2)
        atomicAdd(&g_q1[(threadIdx.x-C1)*64], (double)bacc[threadIdx.x]);
}

__global__ void k_fin1(const float* __restrict__ g, const float* __restrict__ b) {
    int c = threadIdx.x;
    if (c >= C1) return;
    double N = (double)NB*HH*WW;
    double m = g_s1[c*64] / N;
    double v = g_q1[c*64] / N - m*m;
    float sc = g[c] * rsqrtf((float)v + EPSV);
    g_bn1s[c] = sc;
    g_bn1b[c] = b[c] - (float)m * sc;
}

// ---------------- conv2 Winograd F(2x2,3x3) + BN1/ReLU in + stats + pool ----
// block: 16x16 output region of one image = 8x8 Winograd tiles (= 8x8 pooled px).
// thread: 6 co x 2 tiles (warp = co-group, lane = tile pair).
__global__ void __launch_bounds__(256, 2) k_conv2w(const float* __restrict__ bias) {
    __shared__ __align__(16) float Is[C1*360];   // 24ci x 18 rows x stride20 = 34.6KB
    __shared__ __align__(16) float Vp[C1*64];    // per-p V: 24ci x 64 tiles = 6KB
    __shared__ __align__(16) float Us[C1*C2];    // per-p U: 24ci x 48co = 4.6KB
    __shared__ float b1s_[C1], b1b_[C1];

    if (threadIdx.x < C1) {
        b1s_[threadIdx.x] = g_bn1s[threadIdx.x];
        b1b_[threadIdx.x] = g_bn1b[threadIdx.x];
    }
    __syncthreads();

    int blk = blockIdx.x;                 // 64 * 49
    int b   = blk / 49;
    int rem = blk - b*49;
    int by  = rem / 7;
    int bx  = rem - by*7;
    int oy0 = by*16, ox0 = bx*16;         // output-pixel origin of region

    // stage 18x18 input patch per ci with BN1+ReLU
    const float* x1b = g_x1 + b*C1*H2*H2;
    for (int i = threadIdx.x; i < C1*324; i += 256) {
        int ci = i / 324;
        int r2 = i - ci*324;
        int r  = r2 / 18;
        int c  = r2 - r*18;
        int gy = oy0 - 1 + r;
        int gx = ox0 - 1 + c;
        float v = ((unsigned)gy < H2 && (unsigned)gx < H2) ? x1b[(ci*H2 + gy)*H2 + gx] : 0.f;
        Is[ci*360 + r*20 + c] = fmaxf(fmaf(v, b1s_[ci], b1b_[ci]), 0.f);
    }

    int lane  = threadIdx.x & 31;
    int warp  = threadIdx.x >> 5;
    int warp6 = warp*6;
    int lane2 = lane*2;

    float y[6][2][4];                     // [co][tile][yi*2+yj]
#pragma unroll
    for (int j = 0; j < 6; j++)
#pragma unroll
    for (int i = 0; i < 2; i++) {
        y[j][i][0] = 0.f; y[j][i][1] = 0.f; y[j][i][2] = 0.f; y[j][i][3] = 0.f;
    }

    // B^T nonzero tables: row p -> two (index, sign) pairs
    const int   IA[4] = {0, 1, 1, 1};
    const int   IB[4] = {2, 2, 2, 3};
    const float SA[4] = {1.f, 1.f, -1.f, 1.f};
    const float SB[4] = {-1.f, 1.f, 1.f, -1.f};
    // A^T coefficients (0, +-1)
    const int AT0[4] = {1, 1, 1, 0};
    const int AT1[4] = {0, 1, -1, -1};

#pragma unroll
    for (int pr = 0; pr < 4; pr++) {
#pragma unroll
        for (int pc = 0; pc < 4; pc++) {
            int p = pr*4 + pc;
            __syncthreads();
            // ---- fill V[p][ci][t] = s-weighted sum of 4 d taps ----
            {
                int ar0 = IA[pr]*20, ar1 = IB[pr]*20;
                int ac0 = IA[pc],    ac1 = IB[pc];
                float sr0 = SA[pr], sr1 = SB[pr];
                float sc0 = SA[pc], sc1 = SB[pc];
#pragma unroll
                for (int k = 0; k < 6; k++) {
                    int v  = threadIdx.x + k*256;
                    int ci = v >> 6;
                    int t  = v & 63;
                    int ty = t >> 3, tx = t & 7;
                    const float* dP = Is + ci*360 + (2*ty)*20 + 2*tx;
                    float d00 = dP[ar0 + ac0], d01 = dP[ar0 + ac1];
                    float d10 = dP[ar1 + ac0], d11 = dP[ar1 + ac1];
                    Vp[v] = sr0*(sc0*d00 + sc1*d01) + sr1*(sc0*d10 + sc1*d11);
                }
                const float* Ug = g_U + p*C1*C2;
#pragma unroll
                for (int k = 0; k < 5; k++) {
                    int v = threadIdx.x + k*256;
                    if (v < C1*C2) Us[v] = Ug[v];
                }
            }
            __syncthreads();
            // ---- M[p] = sum_ci U[p] * V[p]   (6 co x 2 tiles per thread) ----
            float m00=0.f, m01=0.f, m10=0.f, m11=0.f, m20=0.f, m21=0.f;
            float m30=0.f, m31=0.f, m40=0.f, m41=0.f, m50=0.f, m51=0.f;
#pragma unroll 6
            for (int ci = 0; ci < C1; ci++) {
                float2 vv = *(const float2*)&Vp[ci*64 + lane2];
                const float* up = &Us[ci*C2 + warp6];
                float2 u0 = *(const float2*)(up);
                float2 u1 = *(const float2*)(up + 2);
                float2 u2 = *(const float2*)(up + 4);
                m00 = fmaf(u0.x, vv.x, m00); m01 = fmaf(u0.x, vv.y, m01);
                m10 = fmaf(u0.y, vv.x, m10); m11 = fmaf(u0.y, vv.y, m11);
                m20 = fmaf(u1.x, vv.x, m20); m21 = fmaf(u1.x, vv.y, m21);
                m30 = fmaf(u1.y, vv.x, m30); m31 = fmaf(u1.y, vv.y, m31);
                m40 = fmaf(u2.x, vv.x, m40); m41 = fmaf(u2.x, vv.y, m41);
                m50 = fmaf(u2.y, vv.x, m50); m51 = fmaf(u2.y, vv.y, m51);
            }
            // ---- Y += (A^T ox A^T)[p] * M[p]  (coeffs 0,+-1; folded at compile) ----
            float mm[6][2] = {{m00,m01},{m10,m11},{m20,m21},{m30,m31},{m40,m41},{m50,m51}};
            int c00 = AT0[pr]*AT0[pc];
            int c01 = AT0[pr]*AT1[pc];
            int c10 = AT1[pr]*AT0[pc];
            int c11 = AT1[pr]*AT1[pc];
#pragma unroll
            for (int j = 0; j < 6; j++)
#pragma unroll
            for (int i = 0; i < 2; i++) {
                float v = mm[j][i];
                if (c00 ==  1) y[j][i][0] += v;
                if (c00 == -1) y[j][i][0] -= v;
                if (c01 ==  1) y[j][i][1] += v;
                if (c01 == -1) y[j][i][1] -= v;
                if (c10 ==  1) y[j][i][2] += v;
                if (c10 == -1) y[j][i][2] -= v;
                if (c11 ==  1) y[j][i][3] += v;
                if (c11 == -1) y[j][i][3] -= v;
            }
        }
    }

    // ---- epilogue: bias, stats, pool (tile == pool window), store ----------
    int ty = lane2 >> 3, tx = lane2 & 7;     // tile coords of first tile (tx even)
    int pooy = by*8 + ty, poox = bx*8 + tx;
#pragma unroll
    for (int j = 0; j < 6; j++) {
        int co = warp6 + j;
        float bco = __ldg(&bias[co]);
        float s = 0.f, qq = 0.f;
        float pooled[2];
#pragma unroll
        for (int i = 0; i < 2; i++) {
            float v0 = y[j][i][0] + bco;
            float v1 = y[j][i][1] + bco;
            float v2 = y[j][i][2] + bco;
            float v3 = y[j][i][3] + bco;
            s += (v0+v1) + (v2+v3);
            qq = fmaf(v0,v0, fmaf(v1,v1, fmaf(v2,v2, fmaf(v3,v3, qq))));
            pooled[i] = fmaxf(fmaxf(v0, v1), fmaxf(v2, v3));
        }
        float* dst = g_x2 + ((b*C2 + co)*H4 + pooy)*H4 + poox;
        *(float2*)dst = make_float2(pooled[0], pooled[1]);
        for (int o = 16; o > 0; o >>= 1) {
            s  += __shfl_down_sync(0xffffffffu, s,  o);
            qq += __shfl_down_sync(0xffffffffu, qq, o);
        }
        if (lane == 0) {
            atomicAdd(&g_s2[co*64], (double)s);
            atomicAdd(&g_q2[co*64], (double)qq);
        }
    }
}

__global__ void k_fin2(const float* __restrict__ g, const float* __restrict__ b) {
    int c = threadIdx.x;
    if (c >= C2) return;
    double N = (double)NB*H2*H2;
    double m = g_s2[c*64] / N;
    double v = g_q2[c*64] / N - m*m;
    float sc = g[c] * rsqrtf((float)v + EPSV);
    g_bn2s[c] = sc;
    g_bn2b[c] = b[c] - (float)m * sc;
}

// ---------------- feat GEMM split-K, BN2+ReLU fused into x2 load ------------
__global__ void __launch_bounds__(256) k_feat_part(const float* __restrict__ fw) {
    __shared__ float xs[NB*33];
    __shared__ float wsm[C2*33];
    int k0  = blockIdx.x * KCH;
    int tid = threadIdx.x;
    int bi  = tid & 15;
    int oi  = tid >> 4;
    int kl  = tid & 31;
    int rr  = tid >> 5;
    float acc[4][3];
#pragma unroll
    for (int i = 0; i < 4; i++)
#pragma unroll
    for (int j = 0; j < 3; j++) acc[i][j] = 0.f;

#pragma unroll 1
    for (int kk = 0; kk < KCH; kk += 32) {
        __syncthreads();
        int kidx = k0 + kk + kl;
        int ch   = kidx / (H4*H4);
        float sc = g_bn2s[ch], sh = g_bn2b[ch];
#pragma unroll
        for (int r = 0; r < 8; r++) {
            int bb = r*8 + rr;
            float raw = g_x2[bb*K2LEN + kidx];
            xs[bb*33 + kl] = fmaxf(fmaf(raw, sc, sh), 0.f);
        }
#pragma unroll
        for (int r = 0; r < 6; r++) {
            int oo = r*8 + rr;
            wsm[oo*33 + kl] = fw[(size_t)oo*K2LEN + kidx];
        }
        __syncthreads();
#pragma unroll
        for (int k = 0; k < 32; k++) {
            float xv[4], wv[3];
#pragma unroll
            for (int i = 0; i < 4; i++) xv[i] = xs[(bi*4 + i)*33 + k];
#pragma unroll
            for (int j = 0; j < 3; j++) wv[j] = wsm[(oi*3 + j)*33 + k];
#pragma unroll
            for (int i = 0; i < 4; i++)
#pragma unroll
            for (int j = 0; j < 3; j++)
                acc[i][j] = fmaf(xv[i], wv[j], acc[i][j]);
        }
    }
#pragma unroll
    for (int i = 0; i < 4; i++)
#pragma unroll
    for (int j = 0; j < 3; j++)
        g_part[(size_t)blockIdx.x*NB*C2 + (bi*4 + i)*C2 + (oi*3 + j)] = acc[i][j];
}

__global__ void k_feat_reduce(const float* __restrict__ fb) {
    int i = blockIdx.x*256 + threadIdx.x;
    if (i >= NB*C2) return;
    float s = 0.f;
    for (int n = 0; n < NCHUNK; n++) s += g_part[n*NB*C2 + i];
    g_feat[i] = s + fb[i % C2];
}

// ---------------- MLP head + theta build + tail outputs ---------------------
__global__ void k_head(const float* __restrict__ l1w, const float* __restrict__ l1b,
                       const float* __restrict__ l2w, const float* __restrict__ l2b,
                       float* __restrict__ out) {
    int b = threadIdx.x;
    if (b >= NB) return;
    float h[24];
#pragma unroll 1
    for (int j = 0; j < 24; j++) {
        float s = l1b[j];
        for (int k = 0; k < 48; k++)
            s = fmaf(l1w[j*48 + k], g_feat[b*48 + k], s);
        h[j] = fmaxf(s, 0.f);
    }
    float t[4];
#pragma unroll
    for (int i = 0; i < 4; i++) {
        float s = l2b[i];
#pragma unroll
        for (int j = 0; j < 24; j++)
            s = fmaf(l2w[i*24 + j], h[j], s);
        t[i] = s;
    }
    float tx = t[0], tyv = t[1], sc = t[2], an = t[3];
    float cs = cosf(an), sn = sinf(an);
    g_theta[b*6 + 0] =  sc*cs;
    g_theta[b*6 + 1] = -sc*sn;
    g_theta[b*6 + 2] =  tx;
    g_theta[b*6 + 3] =  sc*sn;
    g_theta[b*6 + 4] =  sc*cs;
    g_theta[b*6 + 5] =  tyv;
    out[NB*HH*WW +         b] = tx;
    out[NB*HH*WW +  64 +   b] = tyv;
    out[NB*HH*WW + 128 +   b] = sc;
    out[NB*HH*WW + 192 +   b] = an;
}

// ---------------- affine grid + bilinear sample -----------------------------
__device__ __forceinline__ float tapf(const float* __restrict__ xb,
                                      float xf, float yf, float wgt) {
    bool valid = (xf >= 0.f) & (xf < (float)WW) & (yf >= 0.f) & (yf < (float)HH);
    int xi = (int)fminf(fmaxf(xf, 0.f), (float)(WW-1));
    int yi = (int)fminf(fmaxf(yf, 0.f), (float)(HH-1));
    float v = __ldg(&xb[yi*WW + xi]);
    return valid ? v*wgt : 0.f;
}

__global__ void k_sample(const float* __restrict__ x, float* __restrict__ out) {
    int idx = blockIdx.x*256 + threadIdx.x;      // 64*224*224 exact
    int b   = idx / (HH*WW);
    int rem = idx - b*(HH*WW);
    int r   = rem / WW;
    int c   = rem - r*WW;
    float xsn = (2.f*c + 1.f)/(float)WW - 1.f;
    float ysn = (2.f*r + 1.f)/(float)HH - 1.f;
    const float* th = g_theta + b*6;
    float gx = th[0]*xsn + th[1]*ysn + th[2];
    float gy = th[3]*xsn + th[4]*ysn + th[5];
    float ix = ((gx + 1.f)*(float)WW - 1.f)*0.5f;
    float iy = ((gy + 1.f)*(float)HH - 1.f)*0.5f;
    float x0 = floorf(ix), y0 = floorf(iy);
    float x1 = x0 + 1.f,   y1 = y0 + 1.f;
    float wx1 = ix - x0, wx0 = 1.f - wx1;
    float wy1 = iy - y0, wy0 = 1.f - wy1;
    const float* xb = x + b*HH*WW;
    float o = tapf(xb, x0, y0, wx0*wy0)
            + tapf(xb, x1, y0, wx1*wy0)
            + tapf(xb, x0, y1, wx0*wy1)
            + tapf(xb, x1, y1, wx1*wy1);
    out[idx] = o;
}

// ---------------- launch ----------------------------------------------------
extern "C" void kernel_launch(void* const* d_in, const int* in_sizes, int n_in,
                              void* d_out, int out_size) {
    (void)in_sizes; (void)n_in; (void)out_size;
    const float* x    = (const float*)d_in[0];
    const float* c1w  = (const float*)d_in[1];
    const float* c1b  = (const float*)d_in[2];
    const float* bn1g = (const float*)d_in[3];
    const float* bn1b = (const float*)d_in[4];
    const float* c2w  = (const float*)d_in[5];
    const float* c2b  = (const float*)d_in[6];
    const float* bn2g = (const float*)d_in[7];
    const float* bn2b = (const float*)d_in[8];
    const float* fw   = (const float*)d_in[9];
    const float* fb   = (const float*)d_in[10];
    const float* l1w  = (const float*)d_in[11];
    const float* l1b  = (const float*)d_in[12];
    const float* l2w  = (const float*)d_in[13];
    const float* l2b  = (const float*)d_in[14];
    float* out = (float*)d_out;

    k_zero<<<12, 256>>>();
    k_prep<<<5, 256>>>(c2w);
    k_conv1<<<3136, 256>>>(x, c1w, c1b);
    k_fin1<<<1, 32>>>(bn1g, bn1b);
    k_conv2w<<<NB*49, 256>>>(c2b);
    k_fin2<<<1, 64>>>(bn2g, bn2b);
    k_feat_part<<<NCHUNK, 256>>>(fw);
    k_feat_reduce<<<12, 256>>>(fb);
    k_head<<<1, 64>>>(l1w, l1b, l2w, l2b, out);
    k_sample<<<(NB*HH*WW)/256, 256>>>(x, out);
}